// round 8
// baseline (speedup 1.0000x reference)
#include <cuda_runtime.h>
#include <cstdint>

// Problem constants (dataset-fixed)
#define D 128
#define BATCH 2
#define MAXN 50000
#define MAXBN (BATCH * MAXN)
#define MAXE 800000
#define LN_EPS 1e-5f

// Scratch buffers
__device__ __align__(16) float g_m[MAXBN * D];    // h @ W_msg^T
__device__ __align__(16) float g_agg[MAXBN * D];  // gathered aggregate
__device__ __align__(16) float g_Wm[D * D];       // W_msg, tf32-rounded
__device__ __align__(16) float g_Wu[D * 2 * D];   // W_upd, tf32-rounded

// CSR-by-target scratch
__device__ int g_cnt[MAXN];
__device__ int g_excl[MAXN];
__device__ int g_blksum[256];
__device__ int g_rowptr[MAXN + 1];
__device__ int g_cursor[MAXN];
__device__ int g_perm[MAXE];

#define SCAN_BLK 256

// ---- tf32 round-to-nearest (RNA via bit trick) -----------------------------
__device__ __forceinline__ float tf32_rn(float x) {
    uint32_t b = __float_as_uint(x);
    b = (b + 0x00001000u) & 0xFFFFE000u;
    return __uint_as_float(b);
}

// ---- warp-level TF32 MMA (sm_80+ baseline PTX; maps to HMMA) ---------------
__device__ __forceinline__ void mma_tf32(float c[4],
                                         uint32_t a0, uint32_t a1,
                                         uint32_t a2, uint32_t a3,
                                         uint32_t b0, uint32_t b1) {
    asm volatile(
        "mma.sync.aligned.m16n8k8.row.col.f32.tf32.tf32.f32 "
        "{%0,%1,%2,%3}, {%4,%5,%6,%7}, {%8,%9}, {%0,%1,%2,%3};"
        : "+f"(c[0]), "+f"(c[1]), "+f"(c[2]), "+f"(c[3])
        : "r"(a0), "r"(a1), "r"(a2), "r"(a3), "r"(b0), "r"(b1));
}

// smem: A tile [128m][132k-packed] + B tile [128n][132k-packed] floats
// packed layout within a row: word for logical k sits at
//   pos(k) = (k>>3)*8 + (k&3)*2 + ((k>>2)&1)
// so the (k, k+4) tf32 fragment pair is one aligned 8-byte LDS.
#define TS 132
#define TS2 66                      // TS/2, for uint2 indexing
#define SM_A_OFF 0
#define SM_B_OFF (128 * TS)
#define SMEM_MMA ((2 * 128 * TS) * sizeof(float))   // 135168 B

// ============================================================================
// prep: zero counters + tf32-round weights
// ============================================================================
__global__ void prep_kernel(const float* __restrict__ Wm,
                            const float* __restrict__ Wu, int N) {
    int i = blockIdx.x * blockDim.x + threadIdx.x;  // >= 50176 threads
    if (i < N) g_cnt[i] = 0;
    if (i < 256) g_blksum[i] = 0;
    if (i < D * D) g_Wm[i] = tf32_rn(Wm[i]);
    if (i < 2 * D * D) g_Wu[i] = tf32_rn(Wu[i]);
}

// ============================================================================
// CSR build (histogram -> scan1 -> merged scan23 -> permutation scatter)
// ============================================================================
__global__ void hist_kernel(const int* __restrict__ tgt, int E) {
    int i = blockIdx.x * blockDim.x + threadIdx.x;
    if (i < E) atomicAdd(&g_cnt[tgt[i]], 1);
}

__global__ void scan1_kernel(int N) {
    __shared__ int s[SCAN_BLK];
    int t = threadIdx.x;
    int i = blockIdx.x * SCAN_BLK + t;
    int v = (i < N) ? g_cnt[i] : 0;
    s[t] = v; __syncthreads();
    #pragma unroll
    for (int off = 1; off < SCAN_BLK; off <<= 1) {
        int x = (t >= off) ? s[t - off] : 0;
        __syncthreads();
        s[t] += x; __syncthreads();
    }
    if (i < N) g_excl[i] = s[t] - v;
    if (t == SCAN_BLK - 1) g_blksum[blockIdx.x] = s[t];
}

__global__ void scan23_kernel(int N, int E) {
    __shared__ int s[SCAN_BLK];
    int t = threadIdx.x;
    int b = blockIdx.x;
    s[t] = (t < b) ? g_blksum[t] : 0;
    __syncthreads();
    #pragma unroll
    for (int off = SCAN_BLK / 2; off > 0; off >>= 1) {
        if (t < off) s[t] += s[t + off];
        __syncthreads();
    }
    int offset = s[0];
    int i = b * SCAN_BLK + t;
    if (i < N) {
        int rp = g_excl[i] + offset;
        g_rowptr[i] = rp;
        g_cursor[i] = rp;
    }
    if (b == 0 && t == 0) g_rowptr[N] = E;
}

__global__ void scatter_perm_kernel(const int* __restrict__ tgt, int E) {
    int i = blockIdx.x * blockDim.x + threadIdx.x;
    if (i < E) {
        int pos = atomicAdd(&g_cursor[tgt[i]], 1);
        g_perm[pos] = i;
    }
}

// ============================================================================
// Gather: one warp per target node, both batches, no atomics (round-5 winner)
// ============================================================================
__global__ __launch_bounds__(256) void gather_kernel(
    const float* __restrict__ rel_emb,
    const int* __restrict__ src, const int* __restrict__ rel, int N)
{
    int w = blockIdx.x * 8 + (threadIdx.x >> 5);
    int lane = threadIdx.x & 31;
    if (w >= N) return;

    int beg = g_rowptr[w];
    int end = g_rowptr[w + 1];

    float4 a0 = make_float4(0.f, 0.f, 0.f, 0.f);
    float4 a1 = make_float4(0.f, 0.f, 0.f, 0.f);

    for (int chunk = beg; chunk < end; chunk += 32) {
        int myE = chunk + lane;
        int ms = 0, mr = 0;
        if (myE < end) {
            int id = g_perm[myE];
            ms = __ldg(&src[id]);
            mr = __ldg(&rel[id]);
        }
        int cnt = min(32, end - chunk);
        #pragma unroll 4
        for (int j = 0; j < cnt; j++) {
            int s = __shfl_sync(0xFFFFFFFFu, ms, j);
            int r = __shfl_sync(0xFFFFFFFFu, mr, j);
            float4 rv = *(const float4*)&rel_emb[r * D + lane * 4];
            float4 m0 = *(const float4*)&g_m[s * D + lane * 4];
            float4 m1 = *(const float4*)&g_m[(N + s) * D + lane * 4];
            a0.x += m0.x * rv.x; a0.y += m0.y * rv.y;
            a0.z += m0.z * rv.z; a0.w += m0.w * rv.w;
            a1.x += m1.x * rv.x; a1.y += m1.y * rv.y;
            a1.z += m1.z * rv.z; a1.w += m1.w * rv.w;
        }
    }

    *(float4*)&g_agg[w * D + lane * 4] = a0;
    *(float4*)&g_agg[(N + w) * D + lane * 4] = a1;
}

// ============================================================================
// Tile loaders (packed k-pair layout)
// Each thread handles (row, kstep): 2 float4 LDG -> register shuffle ->
// 2 float4 STS at packed positions ks*8 and ks*8+4.
// ============================================================================
__device__ __forceinline__ void load_a_tile(float* As, const float* __restrict__ X,
                                            int ldx, int row0, int limit, int tid) {
    #pragma unroll
    for (int it = tid; it < 2048; it += 256) {       // 128 rows x 16 ksteps
        int m = it >> 4;
        int ks = it & 15;
        int row = row0 + m;
        float4 lo = make_float4(0.f, 0.f, 0.f, 0.f);
        float4 hi = make_float4(0.f, 0.f, 0.f, 0.f);
        if (row < limit) {
            lo = *(const float4*)&X[(long)row * ldx + ks * 8];
            hi = *(const float4*)&X[(long)row * ldx + ks * 8 + 4];
        }
        float4 p0 = make_float4(tf32_rn(lo.x), tf32_rn(hi.x),
                                tf32_rn(lo.y), tf32_rn(hi.y));
        float4 p1 = make_float4(tf32_rn(lo.z), tf32_rn(hi.z),
                                tf32_rn(lo.w), tf32_rn(hi.w));
        *(float4*)&As[m * TS + ks * 8]     = p0;
        *(float4*)&As[m * TS + ks * 8 + 4] = p1;
    }
}

__device__ __forceinline__ void load_b_tile(float* Bs, const float* __restrict__ W,
                                            int ldw, int koff, int tid) {
    #pragma unroll
    for (int it = tid; it < 2048; it += 256) {
        int n = it >> 4;
        int ks = it & 15;
        float4 lo = *(const float4*)&W[(long)n * ldw + koff + ks * 8];
        float4 hi = *(const float4*)&W[(long)n * ldw + koff + ks * 8 + 4];
        *(float4*)&Bs[n * TS + ks * 8]     = make_float4(lo.x, hi.x, lo.y, hi.y);
        *(float4*)&Bs[n * TS + ks * 8 + 4] = make_float4(lo.z, hi.z, lo.w, hi.w);
    }
}

// ============================================================================
// Warp-tile MMA: warp owns 32 rows (m0) x 64 cols (n0).
// c[mt][nt][4]: mt in {0,1} (16-row tiles), nt in 0..7 (8-col tiles).
// ============================================================================
__device__ __forceinline__ void mma_tile(float c[2][8][4],
                                         const uint2* A2, const uint2* B2,
                                         int m0, int n0, int gid, int tg) {
    #pragma unroll 1
    for (int ks = 0; ks < 16; ks++) {
        int ko = ks * 4 + tg;
        uint2 aL0 = A2[(m0 + gid) * TS2 + ko];
        uint2 aH0 = A2[(m0 + gid + 8) * TS2 + ko];
        uint2 aL1 = A2[(m0 + gid + 16) * TS2 + ko];
        uint2 aH1 = A2[(m0 + gid + 24) * TS2 + ko];
        uint2 b[8];
        #pragma unroll
        for (int nt = 0; nt < 8; nt++)
            b[nt] = B2[(n0 + nt * 8 + gid) * TS2 + ko];
        #pragma unroll
        for (int nt = 0; nt < 8; nt++) {
            mma_tf32(c[0][nt], aL0.x, aH0.x, aL0.y, aH0.y, b[nt].x, b[nt].y);
            mma_tf32(c[1][nt], aL1.x, aH1.x, aL1.y, aH1.y, b[nt].x, b[nt].y);
        }
    }
}

// ============================================================================
// GEMM 1: g_m = h @ W_msg^T   (tile 128x128, K=128)
// ============================================================================
__global__ __launch_bounds__(256) void gemm_msg_mma(
    const float* __restrict__ h, int BN)
{
    extern __shared__ float sm[];
    float* As = sm + SM_A_OFF;
    float* Bs = sm + SM_B_OFF;

    int tid = threadIdx.x;
    int lane = tid & 31, warp = tid >> 5;
    int gid = lane >> 2, tg = lane & 3;
    int m0 = (warp >> 1) * 32;
    int n0 = (warp & 1) * 64;
    int row0 = blockIdx.x * 128;

    float c[2][8][4];
    #pragma unroll
    for (int mt = 0; mt < 2; mt++)
        #pragma unroll
        for (int nt = 0; nt < 8; nt++)
            #pragma unroll
            for (int q = 0; q < 4; q++) c[mt][nt][q] = 0.f;

    load_a_tile(As, h, D, row0, BN, tid);
    load_b_tile(Bs, g_Wm, D, 0, tid);
    __syncthreads();

    mma_tile(c, (const uint2*)As, (const uint2*)Bs, m0, n0, gid, tg);

    #pragma unroll
    for (int mt = 0; mt < 2; mt++) {
        int r0 = row0 + m0 + mt * 16 + gid;
        int r1 = r0 + 8;
        #pragma unroll
        for (int nt = 0; nt < 8; nt++) {
            int col = n0 + nt * 8 + tg * 2;
            if (r0 < BN)
                *(float2*)&g_m[(long)r0 * D + col] = make_float2(c[mt][nt][0], c[mt][nt][1]);
            if (r1 < BN)
                *(float2*)&g_m[(long)r1 * D + col] = make_float2(c[mt][nt][2], c[mt][nt][3]);
        }
    }
}

// ============================================================================
// GEMM 2: out = LN(h + relu([h|agg] @ W_upd^T + b))   (K=256, 2 phases)
// ============================================================================
__global__ __launch_bounds__(256) void gemm_upd_mma(
    const float* __restrict__ h,
    const float* __restrict__ b_upd, const float* __restrict__ ln_s,
    const float* __restrict__ ln_b, float* __restrict__ out, int BN)
{
    extern __shared__ float sm[];
    float* As = sm + SM_A_OFF;
    float* Bs = sm + SM_B_OFF;

    int tid = threadIdx.x;
    int lane = tid & 31, warp = tid >> 5;
    int gid = lane >> 2, tg = lane & 3;
    int m0 = (warp >> 1) * 32;
    int n0 = (warp & 1) * 64;
    int row0 = blockIdx.x * 128;

    float c[2][8][4];
    #pragma unroll
    for (int mt = 0; mt < 2; mt++)
        #pragma unroll
        for (int nt = 0; nt < 8; nt++)
            #pragma unroll
            for (int q = 0; q < 4; q++) c[mt][nt][q] = 0.f;

    #pragma unroll 1
    for (int phase = 0; phase < 2; phase++) {
        const float* X = (phase == 0) ? h : (const float*)g_agg;
        __syncthreads();                    // prior phase reads complete
        load_a_tile(As, X, D, row0, BN, tid);
        load_b_tile(Bs, g_Wu, 2 * D, phase * D, tid);
        __syncthreads();
        mma_tile(c, (const uint2*)As, (const uint2*)Bs, m0, n0, gid, tg);
    }

    // stage C into As region for per-row epilogue
    __syncthreads();
    #pragma unroll
    for (int mt = 0; mt < 2; mt++) {
        int sr0 = m0 + mt * 16 + gid;
        #pragma unroll
        for (int nt = 0; nt < 8; nt++) {
            int col = n0 + nt * 8 + tg * 2;
            *(float2*)&As[sr0 * TS + col]       = make_float2(c[mt][nt][0], c[mt][nt][1]);
            *(float2*)&As[(sr0 + 8) * TS + col] = make_float2(c[mt][nt][2], c[mt][nt][3]);
        }
    }
    __syncthreads();

    if (tid < 128) {
        int row = row0 + tid;
        if (row < BN) {
            float* Crow = &As[tid * TS];
            float sum = 0.f, ssq = 0.f;
            #pragma unroll 4
            for (int n = 0; n < D; n += 4) {
                float4 cv = *(float4*)&Crow[n];
                float4 bu = __ldg((const float4*)&b_upd[n]);
                float4 hr = *(const float4*)&h[(long)row * D + n];
                float v0 = fmaxf(cv.x + bu.x, 0.f) + hr.x;
                float v1 = fmaxf(cv.y + bu.y, 0.f) + hr.y;
                float v2 = fmaxf(cv.z + bu.z, 0.f) + hr.z;
                float v3 = fmaxf(cv.w + bu.w, 0.f) + hr.w;
                *(float4*)&Crow[n] = make_float4(v0, v1, v2, v3);
                sum += v0 + v1 + v2 + v3;
                ssq += v0 * v0 + v1 * v1 + v2 * v2 + v3 * v3;
            }
            float mean = sum * (1.f / (float)D);
            float var  = ssq * (1.f / (float)D) - mean * mean;
            float rstd = rsqrtf(var + LN_EPS);
            #pragma unroll 4
            for (int n = 0; n < D; n += 4) {
                float4 v  = *(float4*)&Crow[n];
                float4 s4 = __ldg((const float4*)&ln_s[n]);
                float4 b4 = __ldg((const float4*)&ln_b[n]);
                float4 o;
                o.x = (v.x - mean) * rstd * s4.x + b4.x;
                o.y = (v.y - mean) * rstd * s4.y + b4.y;
                o.z = (v.z - mean) * rstd * s4.z + b4.z;
                o.w = (v.w - mean) * rstd * s4.w + b4.w;
                *(float4*)&out[(long)row * D + n] = o;
            }
        }
    }
}

// ---------------------------------------------------------------------------
// Launcher
//  0 h [B*N*D] f32, 1 W_msg [D*D], 2 rel_emb [R*D], 3 W_upd [D*2D],
//  4 b_upd [D], 5 ln_scale [D], 6 ln_bias [D],
//  7 edge_src [E] i32, 8 edge_tgt [E] i32, 9 edge_rel [E] i32, 10 nE scalar
// ---------------------------------------------------------------------------
extern "C" void kernel_launch(void* const* d_in, const int* in_sizes, int n_in,
                              void* d_out, int out_size)
{
    const float* h       = (const float*)d_in[0];
    const float* W_msg   = (const float*)d_in[1];
    const float* rel_emb = (const float*)d_in[2];
    const float* W_upd   = (const float*)d_in[3];
    const float* b_upd   = (const float*)d_in[4];
    const float* ln_s    = (const float*)d_in[5];
    const float* ln_b    = (const float*)d_in[6];
    const int*   e_src   = (const int*)d_in[7];
    const int*   e_tgt   = (const int*)d_in[8];
    const int*   e_rel   = (const int*)d_in[9];
    float* out = (float*)d_out;

    int BN = in_sizes[0] / D;      // 100000
    int N  = BN / BATCH;           // 50000
    int E  = in_sizes[7];          // 800000

    (void)cudaFuncSetAttribute(gemm_msg_mma,
        cudaFuncAttributeMaxDynamicSharedMemorySize, (int)SMEM_MMA);
    (void)cudaFuncSetAttribute(gemm_upd_mma,
        cudaFuncAttributeMaxDynamicSharedMemorySize, (int)SMEM_MMA);

    int nb = (N + SCAN_BLK - 1) / SCAN_BLK;   // 196
    int tiles = (BN + 127) / 128;             // 782

    prep_kernel<<<(N + 255) / 256, 256>>>(W_msg, W_upd, N);
    hist_kernel<<<(E + 255) / 256, 256>>>(e_tgt, E);
    scan1_kernel<<<nb, SCAN_BLK>>>(N);
    scan23_kernel<<<nb, SCAN_BLK>>>(N, E);
    scatter_perm_kernel<<<(E + 255) / 256, 256>>>(e_tgt, E);
    gemm_msg_mma<<<tiles, 256, SMEM_MMA>>>(h, BN);
    gather_kernel<<<(N + 7) / 8, 256>>>(rel_emb, e_src, e_rel, N);
    gemm_upd_mma<<<tiles, 256, SMEM_MMA>>>(h, b_upd, ln_s, ln_b, out, BN);
}